// round 2
// baseline (speedup 1.0000x reference)
#include <cuda_runtime.h>
#include <cuda_bf16.h>
#include <math.h>

#define FULLMASK 0xffffffffu

constexpr int T_ = 128;
constexpr int H_ = 128;
constexpr float EPS_ = 1e-5f;
constexpr float R2_ = 0.70710678118654752440f;

__device__ __forceinline__ float warp_sum(float v) {
    v += __shfl_xor_sync(FULLMASK, v, 16);
    v += __shfl_xor_sync(FULLMASK, v, 8);
    v += __shfl_xor_sync(FULLMASK, v, 4);
    v += __shfl_xor_sync(FULLMASK, v, 2);
    v += __shfl_xor_sync(FULLMASK, v, 1);
    return v;
}

__global__ __launch_bounds__(128, 7)
void qlstm_kernel(
    const float* __restrict__ x,     const float* __restrict__ pe,
    const float* __restrict__ emb_w, const float* __restrict__ emb_b,
    const float* __restrict__ emb_g, const float* __restrict__ emb_bt,
    const float* __restrict__ ip_w,  const float* __restrict__ ip_b,
    const float* __restrict__ in_g,  const float* __restrict__ in_b,
    const float* __restrict__ wq_i,  const float* __restrict__ wq_f,
    const float* __restrict__ wq_g,  const float* __restrict__ wq_o,
    const float* __restrict__ pi_w,  const float* __restrict__ pi_b,
    const float* __restrict__ pf_w,  const float* __restrict__ pf_b,
    const float* __restrict__ pg_w,  const float* __restrict__ pg_b,
    const float* __restrict__ po_w,  const float* __restrict__ po_b,
    const float* __restrict__ on_g,  const float* __restrict__ on_b,
    const float* __restrict__ out_w, const float* __restrict__ out_b,
    float* __restrict__ out)
{
    const int b    = blockIdx.x;
    const int tid  = threadIdx.x;      // 0..127
    const int w    = tid >> 5;         // warp: gate index (i,f,g,o)
    const int lane = tid & 31;
    const int h    = tid;              // hidden index

    __shared__ __align__(16) float  sh_x[T_ * 8];         // 4 KB
    __shared__ __align__(16) float  sh_wp[4][32][16];     // 8 KB  interleaved ip_w pairs
    __shared__ __align__(16) float  sh_pw[4][128][8];     // 16 KB gate weights [g][h][j]
    __shared__ __align__(16) float2 sh_wcs[4][4][8];      // 1 KB
    __shared__ __align__(16) float2 sh_incs[8];
    __shared__ __align__(16) float  sh_comb[256];
    __shared__ __align__(16) float  sh_z[4][8];
    __shared__ __align__(16) float2 sh_pj2[4];
    __shared__ __align__(16) float2 sh_redA[4];
    __shared__ __align__(16) float4 sh_redB[4];
    __shared__ float sh_sc[2];
    __shared__ float sh_ing8[8], sh_inb8[8];

    // ---------------- init / staging ----------------
    {
        const float4* xg = (const float4*)(x + (size_t)b * T_ * 8);
        float4* xs = (float4*)sh_x;
        #pragma unroll
        for (int i = tid; i < 256; i += 128) xs[i] = xg[i];
    }
    {
        // interleave ip_w rows 2w, 2w+1 over this lane's 8-chunk
        const float4* r0 = (const float4*)(ip_w + (2 * w) * 256 + lane * 8);
        const float4* r1 = (const float4*)(ip_w + (2 * w + 1) * 256 + lane * 8);
        float4 a0 = r0[0], a1 = r0[1], b0 = r1[0], b1 = r1[1];
        float4* dst = (float4*)&sh_wp[w][lane][0];
        dst[0] = make_float4(a0.x, b0.x, a0.y, b0.y);
        dst[1] = make_float4(a0.z, b0.z, a0.w, b0.w);
        dst[2] = make_float4(a1.x, b1.x, a1.y, b1.y);
        dst[3] = make_float4(a1.z, b1.z, a1.w, b1.w);
    }
    {
        const float* pw[4] = {pi_w, pf_w, pg_w, po_w};
        #pragma unroll
        for (int g = 0; g < 4; g++) {
            const float4* src = (const float4*)(pw[g] + tid * 8);
            float4* d = (float4*)&sh_pw[g][tid][0];
            d[0] = src[0]; d[1] = src[1];
        }
    }
    {
        const float* wq[4] = {wq_i, wq_f, wq_g, wq_o};
        int g = tid >> 5, rem = tid & 31;
        int l = rem >> 3, q = rem & 7;
        float a = 0.5f * wq[g][l * 8 + q];
        sh_wcs[g][l][q] = make_float2(cosf(a), sinf(a));
    }
    if (tid < 8) { sh_ing8[tid] = in_g[tid]; sh_inb8[tid] = in_b[tid]; }

    float embw[8];
    #pragma unroll
    for (int k = 0; k < 8; k++) embw[k] = emb_w[h * 8 + k];
    const float embb  = emb_b[h], embg = emb_g[h], embbt = emb_bt[h];
    const float gw    = on_g[h] * out_w[h];
    const float bw    = on_b[h] * out_w[h];
    const float bi    = pi_b[h], bf = pf_b[h], bg = pg_b[h], bo = po_b[h];
    const float ipb0  = ip_b[2 * w], ipb1 = ip_b[2 * w + 1];

    // S1 = sum(on_g*out_w), C0 = sum(on_b*out_w) + out_b
    {
        float s1 = warp_sum(gw), s2 = warp_sum(bw);
        if (lane == 0) sh_redA[w] = make_float2(s1, s2);
    }
    __syncthreads();
    if (tid == 0) {
        float S1 = 0.f, C0 = 0.f;
        #pragma unroll
        for (int i = 0; i < 4; i++) { S1 += sh_redA[i].x; C0 += sh_redA[i].y; }
        sh_sc[0] = S1; sh_sc[1] = C0 + out_b[0];
    }
    __syncthreads();
    const float S1 = sh_sc[0], C0 = sh_sc[1];

    // combined CNOT lane permutation: src = m_E(m_O(lane))
    //   m_O: bit2^=bit3, bit0^=bit1 ; m_E: bit3^=bit4, bit1^=bit2
    const int mo   = lane ^ ((lane >> 1) & 4) ^ ((lane >> 1) & 1);
    const int psrc = mo   ^ ((mo   >> 1) & 8) ^ ((mo   >> 1) & 2);
    const bool c1  = (lane & 1);   // ctrl4: lane bit0 -> reg bit2

    float hstate = 0.f, cstate = 0.f;
    float* outp = out + (size_t)b * T_;

    for (int t = 0; t < T_; t++) {
        // ---------- Phase A: embedding + LN + pe ----------
        float pe_v = __ldg(pe + t * H_ + h);
        const float4* xv = (const float4*)(sh_x + t * 8);
        float4 xa = xv[0], xb = xv[1];
        float e = embb + xa.x * embw[0] + xa.y * embw[1] + xa.z * embw[2] + xa.w * embw[3]
                       + xb.x * embw[4] + xb.y * embw[5] + xb.z * embw[6] + xb.w * embw[7];
        {
            float s = warp_sum(e), s2 = warp_sum(e * e);
            if (lane == 0) sh_redA[w] = make_float2(s, s2);
        }
        __syncthreads();
        float4 ra = ((const float4*)sh_redA)[0];
        float4 rb = ((const float4*)sh_redA)[1];
        float Sv  = (ra.x + ra.z) + (rb.x + rb.z);
        float Sv2 = (ra.y + ra.w) + (rb.y + rb.w);
        float m   = Sv * (1.f / 128.f);
        float var = Sv2 * (1.f / 128.f) - m * m;
        float inv = rsqrtf(var + EPS_);
        float emb = (e - m) * inv * embg + embbt + pe_v;

        // ---------- Phase B: proj = LN(tanh(comb @ ip_w^T + b)) ----------
        sh_comb[h]       = emb;
        sh_comb[128 + h] = hstate;
        __syncthreads();
        {
            const float4* cb = (const float4*)(sh_comb + lane * 8);
            float4 c0 = cb[0], cv1 = cb[1];
            const float4* wp4 = (const float4*)&sh_wp[w][lane][0];
            float4 q0 = wp4[0], q1 = wp4[1], q2 = wp4[2], q3 = wp4[3];
            float d0 = c0.x * q0.x + c0.y * q0.z + c0.z * q1.x + c0.w * q1.z
                     + cv1.x * q2.x + cv1.y * q2.z + cv1.z * q3.x + cv1.w * q3.z;
            float d1 = c0.x * q0.y + c0.y * q0.w + c0.z * q1.y + c0.w * q1.w
                     + cv1.x * q2.y + cv1.y * q2.w + cv1.z * q3.y + cv1.w * q3.w;
            d0 = warp_sum(d0); d1 = warp_sum(d1);
            if (lane == 0) sh_pj2[w] = make_float2(d0 + ipb0, d1 + ipb1);
        }
        __syncthreads();
        if (w == 0) {
            float pv = tanhf(((const float*)sh_pj2)[lane & 7]);
            float sm = pv, sq = pv * pv;
            sm += __shfl_xor_sync(FULLMASK, sm, 1); sq += __shfl_xor_sync(FULLMASK, sq, 1);
            sm += __shfl_xor_sync(FULLMASK, sm, 2); sq += __shfl_xor_sync(FULLMASK, sq, 2);
            sm += __shfl_xor_sync(FULLMASK, sm, 4); sq += __shfl_xor_sync(FULLMASK, sq, 4);
            float mm = sm * 0.125f;
            float vv = sq * 0.125f - mm * mm;
            float iv = rsqrtf(vv + EPS_);
            float pj = (pv - mm) * iv * sh_ing8[lane & 7] + sh_inb8[lane & 7];
            float a  = 0.5f * pj;
            if (lane < 8) sh_incs[lane] = make_float2(cosf(a), sinf(a));
        }
        __syncthreads();

        // ---------- Phase C: VQC (warp w simulates gate w) ----------
        float st[8];
        {
            const float4* ic = (const float4*)sh_incs;
            float4 i0 = ic[0], i1 = ic[1], i2 = ic[2], i3 = ic[3];
            float f00 = R2_ * (i0.x - i0.y), f01 = R2_ * (i0.x + i0.y);   // q0
            float f10 = R2_ * (i0.z - i0.w), f11 = R2_ * (i0.z + i0.w);   // q1
            float f20 = R2_ * (i1.x - i1.y), f21 = R2_ * (i1.x + i1.y);   // q2
            float f30 = R2_ * (i1.z - i1.w), f31 = R2_ * (i1.z + i1.w);   // q3
            float f40 = R2_ * (i2.x - i2.y), f41 = R2_ * (i2.x + i2.y);   // q4
            float f50 = R2_ * (i2.z - i2.w), f51 = R2_ * (i2.z + i2.w);   // q5
            float f60 = R2_ * (i3.x - i3.y), f61 = R2_ * (i3.x + i3.y);   // q6
            float f70 = R2_ * (i3.z - i3.w), f71 = R2_ * (i3.z + i3.w);   // q7
            // lane bits 0..4 -> qubits 4..0 ; reg bits 0..2 -> qubits 7..5
            float L = ((lane & 1)  ? f41 : f40) * ((lane & 2)  ? f31 : f30)
                    * ((lane & 4)  ? f21 : f20) * ((lane & 8)  ? f11 : f10)
                    * ((lane & 16) ? f01 : f00);
            float m00 = f60 * f70, m01 = f60 * f71, m10 = f61 * f70, m11 = f61 * f71;
            float L0 = L * f50, L1 = L * f51;
            st[0] = L0 * m00; st[1] = L0 * m01; st[2] = L0 * m10; st[3] = L0 * m11;
            st[4] = L1 * m00; st[5] = L1 * m01; st[6] = L1 * m10; st[7] = L1 * m11;
        }

        #pragma unroll
        for (int l = 0; l < 4; l++) {
            // C45: lane bit0 controls reg-bit2 flip
            #pragma unroll
            for (int r = 0; r < 4; r++) {
                float a = st[r], bq = st[r + 4];
                st[r]     = c1 ? bq : a;
                st[r + 4] = c1 ? a  : bq;
            }
            // combined even+odd CNOT lane permutation (one shfl round)
            #pragma unroll
            for (int r = 0; r < 8; r++) st[r] = __shfl_sync(FULLMASK, st[r], psrc);
            // C67: reg bit1 controls reg-bit0 flip
            { float tp = st[2]; st[2] = st[3]; st[3] = tp; tp = st[6]; st[6] = st[7]; st[7] = tp; }
            // C56: reg bit2 controls reg-bit1 flip
            { float tp = st[4]; st[4] = st[6]; st[6] = tp; tp = st[5]; st[5] = st[7]; st[7] = tp; }

            const float4* wc = (const float4*)&sh_wcs[w][l][0];
            float4 wc0 = wc[0], wc1 = wc[1], wc2 = wc[2], wc3 = wc[3];

            // RY lane qubits: q0 bm=16 (wc0.xy), q1 bm=8 (wc0.zw), q2 bm=4 (wc1.xy),
            //                 q3 bm=2 (wc1.zw), q4 bm=1 (wc2.xy)
            {
                float sgn = (lane & 16) ? wc0.y : -wc0.y;
                #pragma unroll
                for (int r = 0; r < 8; r++) {
                    float o = __shfl_xor_sync(FULLMASK, st[r], 16);
                    st[r] = fmaf(sgn, o, wc0.x * st[r]);
                }
            }
            {
                float sgn = (lane & 8) ? wc0.w : -wc0.w;
                #pragma unroll
                for (int r = 0; r < 8; r++) {
                    float o = __shfl_xor_sync(FULLMASK, st[r], 8);
                    st[r] = fmaf(sgn, o, wc0.z * st[r]);
                }
            }
            {
                float sgn = (lane & 4) ? wc1.y : -wc1.y;
                #pragma unroll
                for (int r = 0; r < 8; r++) {
                    float o = __shfl_xor_sync(FULLMASK, st[r], 4);
                    st[r] = fmaf(sgn, o, wc1.x * st[r]);
                }
            }
            {
                float sgn = (lane & 2) ? wc1.w : -wc1.w;
                #pragma unroll
                for (int r = 0; r < 8; r++) {
                    float o = __shfl_xor_sync(FULLMASK, st[r], 2);
                    st[r] = fmaf(sgn, o, wc1.z * st[r]);
                }
            }
            {
                float sgn = (lane & 1) ? wc2.y : -wc2.y;
                #pragma unroll
                for (int r = 0; r < 8; r++) {
                    float o = __shfl_xor_sync(FULLMASK, st[r], 1);
                    st[r] = fmaf(sgn, o, wc2.x * st[r]);
                }
            }
            // RY q5 (reg bit2): pairs (r, r+4)
            #pragma unroll
            for (int r = 0; r < 4; r++) {
                float a0 = st[r], a1 = st[r + 4];
                st[r]     = wc2.z * a0 - wc2.w * a1;
                st[r + 4] = wc2.w * a0 + wc2.z * a1;
            }
            // RY q6 (reg bit1): pairs (r, r+2), r in {0,1,4,5}
            {
                float a0, a1;
                a0 = st[0]; a1 = st[2]; st[0] = wc3.x * a0 - wc3.y * a1; st[2] = wc3.y * a0 + wc3.x * a1;
                a0 = st[1]; a1 = st[3]; st[1] = wc3.x * a0 - wc3.y * a1; st[3] = wc3.y * a0 + wc3.x * a1;
                a0 = st[4]; a1 = st[6]; st[4] = wc3.x * a0 - wc3.y * a1; st[6] = wc3.y * a0 + wc3.x * a1;
                a0 = st[5]; a1 = st[7]; st[5] = wc3.x * a0 - wc3.y * a1; st[7] = wc3.y * a0 + wc3.x * a1;
            }
            // RY q7 (reg bit0): pairs (2r, 2r+1)
            #pragma unroll
            for (int r = 0; r < 8; r += 2) {
                float a0 = st[r], a1 = st[r + 1];
                st[r]     = wc3.z * a0 - wc3.w * a1;
                st[r + 1] = wc3.w * a0 + wc3.z * a1;
            }
        }

        // ---------- measurement: z_q = sum +-|phi|^2 ----------
        {
            float p0 = st[0]*st[0], p1 = st[1]*st[1], p2 = st[2]*st[2], p3 = st[3]*st[3];
            float p4 = st[4]*st[4], p5 = st[5]*st[5], p6 = st[6]*st[6], p7 = st[7]*st[7];
            float s01 = p0 + p1, s23 = p2 + p3, s45 = p4 + p5, s67 = p6 + p7;
            float d01 = p0 - p1, d23 = p2 - p3, d45 = p4 - p5, d67 = p6 - p7;
            float Tt = (s01 + s23) + (s45 + s67);
            float Z7 = (d01 + d23) + (d45 + d67);
            float Z6 = (s01 - s23) + (s45 - s67);
            float Z5 = (s01 + s23) - (s45 + s67);
            float zq0, zq1, zq2, zq3, zq4, o;

            o = __shfl_xor_sync(FULLMASK, Tt, 1);
            zq4 = (lane & 1) ? (o - Tt) : (Tt - o); Tt += o;
            Z5 += __shfl_xor_sync(FULLMASK, Z5, 1);
            Z6 += __shfl_xor_sync(FULLMASK, Z6, 1);
            Z7 += __shfl_xor_sync(FULLMASK, Z7, 1);

            o = __shfl_xor_sync(FULLMASK, Tt, 2);
            zq3 = (lane & 2) ? (o - Tt) : (Tt - o); Tt += o;
            zq4 += __shfl_xor_sync(FULLMASK, zq4, 2);
            Z5 += __shfl_xor_sync(FULLMASK, Z5, 2);
            Z6 += __shfl_xor_sync(FULLMASK, Z6, 2);
            Z7 += __shfl_xor_sync(FULLMASK, Z7, 2);

            o = __shfl_xor_sync(FULLMASK, Tt, 4);
            zq2 = (lane & 4) ? (o - Tt) : (Tt - o); Tt += o;
            zq3 += __shfl_xor_sync(FULLMASK, zq3, 4);
            zq4 += __shfl_xor_sync(FULLMASK, zq4, 4);
            Z5 += __shfl_xor_sync(FULLMASK, Z5, 4);
            Z6 += __shfl_xor_sync(FULLMASK, Z6, 4);
            Z7 += __shfl_xor_sync(FULLMASK, Z7, 4);

            o = __shfl_xor_sync(FULLMASK, Tt, 8);
            zq1 = (lane & 8) ? (o - Tt) : (Tt - o); Tt += o;
            zq2 += __shfl_xor_sync(FULLMASK, zq2, 8);
            zq3 += __shfl_xor_sync(FULLMASK, zq3, 8);
            zq4 += __shfl_xor_sync(FULLMASK, zq4, 8);
            Z5 += __shfl_xor_sync(FULLMASK, Z5, 8);
            Z6 += __shfl_xor_sync(FULLMASK, Z6, 8);
            Z7 += __shfl_xor_sync(FULLMASK, Z7, 8);

            o = __shfl_xor_sync(FULLMASK, Tt, 16);
            zq0 = (lane & 16) ? (o - Tt) : (Tt - o);
            zq1 += __shfl_xor_sync(FULLMASK, zq1, 16);
            zq2 += __shfl_xor_sync(FULLMASK, zq2, 16);
            zq3 += __shfl_xor_sync(FULLMASK, zq3, 16);
            zq4 += __shfl_xor_sync(FULLMASK, zq4, 16);
            Z5 += __shfl_xor_sync(FULLMASK, Z5, 16);
            Z6 += __shfl_xor_sync(FULLMASK, Z6, 16);
            Z7 += __shfl_xor_sync(FULLMASK, Z7, 16);

            if (lane == 0) {
                float4* zp = (float4*)&sh_z[w][0];
                zp[0] = make_float4(zq0, zq1, zq2, zq3);
                zp[1] = make_float4(zq4, Z5, Z6, Z7);
            }
        }
        __syncthreads();

        // ---------- Phase D: gates, LSTM update, output LN ----------
        float pre[4] = {bi, bf, bg, bo};
        #pragma unroll
        for (int g = 0; g < 4; g++) {
            const float4* zp = (const float4*)&sh_z[g][0];
            float4 z0 = zp[0], z1 = zp[1];
            const float4* pp = (const float4*)&sh_pw[g][h][0];
            float4 p0 = pp[0], p1 = pp[1];
            pre[g] += z0.x * p0.x + z0.y * p0.y + z0.z * p0.z + z0.w * p0.w
                    + z1.x * p1.x + z1.y * p1.y + z1.z * p1.z + z1.w * p1.w;
        }
        float i_t = 1.f / (1.f + expf(-pre[0]));
        float f_t = 1.f / (1.f + expf(-pre[1]));
        float g_t = tanhf(pre[2]);
        float o_t = 1.f / (1.f + expf(-pre[3]));
        cstate = f_t * cstate + i_t * g_t;
        hstate = o_t * tanhf(cstate);

        float v = hstate + emb;
        {
            float r0 = warp_sum(v), r1 = warp_sum(v * v), r2 = warp_sum(v * gw);
            if (lane == 0) sh_redB[w] = make_float4(r0, r1, r2, 0.f);
        }
        __syncthreads();
        if (tid == 0) {
            float4 b0 = sh_redB[0], b1 = sh_redB[1], b2 = sh_redB[2], b3 = sh_redB[3];
            float Svo = (b0.x + b1.x) + (b2.x + b3.x);
            float Sqo = (b0.y + b1.y) + (b2.y + b3.y);
            float Sgo = (b0.z + b1.z) + (b2.z + b3.z);
            float m2   = Svo * (1.f / 128.f);
            float var2 = Sqo * (1.f / 128.f) - m2 * m2;
            float inv2 = rsqrtf(var2 + EPS_);
            outp[t] = inv2 * (Sgo - m2 * S1) + C0;
        }
    }
}

extern "C" void kernel_launch(void* const* d_in, const int* in_sizes, int n_in,
                              void* d_out, int out_size) {
    const float* p[26];
    for (int i = 0; i < 26; i++) p[i] = (const float*)d_in[i];
    qlstm_kernel<<<1024, 128>>>(
        p[0], p[1], p[2], p[3], p[4], p[5], p[6], p[7], p[8], p[9],
        p[10], p[11], p[12], p[13], p[14], p[15], p[16], p[17], p[18], p[19],
        p[20], p[21], p[22], p[23], p[24], p[25],
        (float*)d_out);
}

// round 5
// speedup vs baseline: 1.0833x; 1.0833x over previous
#include <cuda_runtime.h>
#include <cuda_bf16.h>
#include <math.h>

#define FULLMASK 0xffffffffu
#define SWAPF(a,b) { float _t=(a); (a)=(b); (b)=_t; }

constexpr int T_ = 128;
constexpr int H_ = 128;
constexpr float EPS_ = 1e-5f;
constexpr float R2_ = 0.70710678118654752440f;

__device__ float g_emb[1024 * 128 * 128];   // 64 MB: LN(emb)+pe
__device__ float g_pj[1024 * 128 * 8];      // 4 MB: emb-half of proj dot

__device__ __forceinline__ float warp_sum(float v) {
    v += __shfl_xor_sync(FULLMASK, v, 16);
    v += __shfl_xor_sync(FULLMASK, v, 8);
    v += __shfl_xor_sync(FULLMASK, v, 4);
    v += __shfl_xor_sync(FULLMASK, v, 2);
    v += __shfl_xor_sync(FULLMASK, v, 1);
    return v;
}

// ---------------- kernel 1: embeddings ----------------
__global__ __launch_bounds__(128)
void emb_kernel(const float* __restrict__ x, const float* __restrict__ pe,
                const float* __restrict__ emb_w, const float* __restrict__ emb_b,
                const float* __restrict__ emb_g, const float* __restrict__ emb_bt)
{
    const int e = blockIdx.x, tid = threadIdx.x, w = tid >> 5, lane = tid & 31;
    __shared__ __align__(16) float sx[T_ * 8];
    const float4* xg = (const float4*)(x + (size_t)e * T_ * 8);
    ((float4*)sx)[tid] = xg[tid];
    ((float4*)sx)[tid + 128] = xg[tid + 128];

    float ew[4][8], gb[4], bt[4], bb[4];
    #pragma unroll
    for (int m = 0; m < 4; m++) {
        int h = lane + 32 * m;
        #pragma unroll
        for (int k = 0; k < 8; k++) ew[m][k] = emb_w[h * 8 + k];
        gb[m] = emb_g[h]; bt[m] = emb_bt[h]; bb[m] = emb_b[h];
    }
    __syncthreads();
    for (int it = 0; it < 32; it++) {
        int t = it * 4 + w;
        const float* xr = sx + t * 8;
        float e4[4];
        #pragma unroll
        for (int m = 0; m < 4; m++) {
            float s = bb[m];
            #pragma unroll
            for (int k = 0; k < 8; k++) s += xr[k] * ew[m][k];
            e4[m] = s;
        }
        float s = (e4[0]+e4[1])+(e4[2]+e4[3]);
        float q = (e4[0]*e4[0]+e4[1]*e4[1])+(e4[2]*e4[2]+e4[3]*e4[3]);
        s = warp_sum(s); q = warp_sum(q);
        float m_ = s * (1.f/128.f);
        float inv = rsqrtf(q * (1.f/128.f) - m_*m_ + EPS_);
        #pragma unroll
        for (int m = 0; m < 4; m++) {
            int h = lane + 32 * m;
            g_emb[(size_t)e*T_*H_ + t*H_ + h] = (e4[m]-m_)*inv*gb[m] + bt[m] + __ldg(pe + t*H_ + h);
        }
    }
}

// ---------------- kernel 2: emb-half of proj dot ----------------
__global__ __launch_bounds__(128)
void pj_kernel(const float* __restrict__ ip_w)
{
    const int e = blockIdx.x, tid = threadIdx.x, w = tid >> 5, lane = tid & 31;
    __shared__ float2 sw[4][128];
    for (int i = tid; i < 512; i += 128) {
        int wp = i >> 7, k = i & 127;
        sw[wp][k] = make_float2(ip_w[2*wp*256 + k], ip_w[(2*wp+1)*256 + k]);
    }
    __syncthreads();
    const float* eb = g_emb + (size_t)e * T_ * H_;
    for (int t = 0; t < T_; t++) {
        const float* er = eb + t * H_;
        float d0 = 0.f, d1 = 0.f;
        #pragma unroll
        for (int i = 0; i < 4; i++) {
            int k = lane + 32 * i;
            float v = er[k]; float2 p = sw[w][k];
            d0 += v * p.x; d1 += v * p.y;
        }
        d0 = warp_sum(d0); d1 = warp_sum(d1);
        if (lane == 0) ((float2*)(g_pj + ((size_t)e*T_ + t)*8))[w] = make_float2(d0, d1);
    }
}

// ---------------- kernel 3: recurrence (4 elems/CTA) ----------------
__global__ __launch_bounds__(128, 2)
void qlstm_kernel(
    const float* __restrict__ ip_w,  const float* __restrict__ ip_b,
    const float* __restrict__ in_g,  const float* __restrict__ in_b,
    const float* __restrict__ wq_i,  const float* __restrict__ wq_f,
    const float* __restrict__ wq_g,  const float* __restrict__ wq_o,
    const float* __restrict__ pi_w,  const float* __restrict__ pi_b,
    const float* __restrict__ pf_w,  const float* __restrict__ pf_b,
    const float* __restrict__ pg_w,  const float* __restrict__ pg_b,
    const float* __restrict__ po_w,  const float* __restrict__ po_b,
    const float* __restrict__ on_g,  const float* __restrict__ on_b,
    const float* __restrict__ out_w, const float* __restrict__ out_b,
    float* __restrict__ out)
{
    const int b0 = blockIdx.x * 4;
    const int tid = threadIdx.x, w = tid >> 5, lane = tid & 31;
    const int j = lane >> 3, l = lane & 7, h = tid;

    __shared__ __align__(16) float  sh_hs[4][136];
    __shared__ __align__(16) float2 sh_ipw2[4][128];   // h-half of ip_w, paired
    __shared__ __align__(16) float2 sh_wcs[4][4][8];
    __shared__ __align__(16) float2 sh_incs[4][12];    // padded stride
    __shared__ __align__(16) float2 sh_pj2[4][4];      // [elem][wpair]
    __shared__ __align__(16) float4 sh_z[4][4][2];     // [elem][gate]
    __shared__ __align__(16) float4 sh_redB[4][4];     // [warp][elem]
    __shared__ float sh_sc[2], sh_ing8[8], sh_inb8[8];

    for (int i = tid; i < 512; i += 128) {
        int wp = i >> 7, k = i & 127;
        sh_ipw2[wp][k] = make_float2(ip_w[2*wp*256 + 128 + k], ip_w[(2*wp+1)*256 + 128 + k]);
    }
    {
        const float* wq[4] = {wq_i, wq_f, wq_g, wq_o};
        int g = tid >> 5, rem = tid & 31, ll = rem >> 3, q = rem & 7;
        float a = 0.5f * wq[g][ll * 8 + q];
        sh_wcs[g][ll][q] = make_float2(cosf(a), sinf(a));
    }
    if (tid < 8) { sh_ing8[tid] = in_g[tid]; sh_inb8[tid] = in_b[tid]; }

    float pwr[32];
    {
        const float* pw[4] = {pi_w, pf_w, pg_w, po_w};
        #pragma unroll
        for (int g = 0; g < 4; g++)
            #pragma unroll
            for (int q = 0; q < 8; q++) pwr[g*8+q] = pw[g][h*8+q];
    }
    const float gw = on_g[h]*out_w[h], bwv = on_b[h]*out_w[h];
    const float bi = pi_b[h], bf = pf_b[h], bg = pg_b[h], bo = po_b[h];
    const float ipb0 = ip_b[2*w], ipb1 = ip_b[2*w+1];

    {
        float s1 = warp_sum(gw), s2 = warp_sum(bwv);
        if (lane == 0) sh_redB[w][0] = make_float4(s1, s2, 0.f, 0.f);
    }
    __syncthreads();
    if (tid == 0) {
        float S = 0.f, C = 0.f;
        #pragma unroll
        for (int i = 0; i < 4; i++) { S += sh_redB[i][0].x; C += sh_redB[i][0].y; }
        sh_sc[0] = S; sh_sc[1] = C + out_b[0];
    }
    __syncthreads();
    const float S1 = sh_sc[0], C0 = sh_sc[1];

    // fused lane perm for CNOT c=0 (l1^=l2) then c=1 (l0^=l1'): inverse map
    const int psrc = (lane & 24) | ((lane ^ ((lane >> 1) & 3)) & 7);
    const bool c1 = (lane & 1);    // c=2: qubit2(lane b0) -> flip reg b4

    float h_e[4] = {0,0,0,0}, c_e[4] = {0,0,0,0};
    const size_t estr = (size_t)T_ * H_;
    const float* embbase = g_emb + (size_t)b0 * estr;

    for (int t = 0; t < T_; t++) {
        float emb_e[4];
        #pragma unroll
        for (int e = 0; e < 4; e++) {
            sh_hs[e][h] = h_e[e];
            emb_e[e] = __ldg(embbase + e * estr + t * H_ + h);
        }
        __syncthreads();

        // Phase B: h-half dot + precomputed emb-half
        {
            float d0 = 0.f, d1 = 0.f;
            #pragma unroll
            for (int i = 0; i < 16; i++) {
                float cv = sh_hs[j][l + 8*i];
                float2 p = sh_ipw2[w][l + 8*i];
                d0 += cv * p.x; d1 += cv * p.y;
            }
            d0 += __shfl_xor_sync(FULLMASK, d0, 1); d1 += __shfl_xor_sync(FULLMASK, d1, 1);
            d0 += __shfl_xor_sync(FULLMASK, d0, 2); d1 += __shfl_xor_sync(FULLMASK, d1, 2);
            d0 += __shfl_xor_sync(FULLMASK, d0, 4); d1 += __shfl_xor_sync(FULLMASK, d1, 4);
            if (l == 0) {
                float2 gp = __ldg((const float2*)(g_pj + ((size_t)(b0+j)*T_ + t)*8) + w);
                sh_pj2[j][w] = make_float2(d0 + gp.x + ipb0, d1 + gp.y + ipb1);
            }
        }
        __syncthreads();

        // mini-LN(8) + input angles (warp 0: group j = elem, l = qubit)
        if (w == 0) {
            float pv = tanhf(((const float*)&sh_pj2[j][0])[l]);
            float sm = pv, sq = pv*pv;
            sm += __shfl_xor_sync(FULLMASK, sm, 1); sq += __shfl_xor_sync(FULLMASK, sq, 1);
            sm += __shfl_xor_sync(FULLMASK, sm, 2); sq += __shfl_xor_sync(FULLMASK, sq, 2);
            sm += __shfl_xor_sync(FULLMASK, sm, 4); sq += __shfl_xor_sync(FULLMASK, sq, 4);
            float mm = sm * 0.125f;
            float iv = rsqrtf(sq * 0.125f - mm*mm + EPS_);
            float a = 0.5f * ((pv - mm) * iv * sh_ing8[l] + sh_inb8[l]);
            sh_incs[j][l] = make_float2(cosf(a), sinf(a));
        }
        __syncthreads();

        // Phase C: VQC. lane bits(2,1,0)=qubits(0,1,2); reg bits(4..0)=qubits(3..7)
        float st[32];
        {
            float F0[8], F1[8];
            #pragma unroll
            for (int q = 0; q < 8; q++) {
                float2 cs = sh_incs[j][q];
                F0[q] = R2_ * (cs.x - cs.y); F1[q] = R2_ * (cs.x + cs.y);
            }
            st[0] = ((l&4)?F1[0]:F0[0]) * ((l&2)?F1[1]:F0[1]) * ((l&1)?F1[2]:F0[2]);
            #pragma unroll
            for (int q = 3; q < 8; q++) {
                int s = 1 << (7 - q);
                #pragma unroll
                for (int r = 0; r < 32; r += 2*s) {
                    float v = st[r];
                    st[r] = v * F0[q]; st[r+s] = v * F1[q];
                }
            }
        }

        #pragma unroll
        for (int lyr = 0; lyr < 4; lyr++) {
            // c=2: lane b0 -> flip reg b4
            #pragma unroll
            for (int r = 0; r < 16; r++) {
                float a = st[r], b2 = st[r+16];
                st[r] = c1 ? b2 : a; st[r+16] = c1 ? a : b2;
            }
            // c=4: reg b3 -> flip reg b2
            #pragma unroll
            for (int r = 0; r < 32; r++) if ((r & 8) && !(r & 4)) SWAPF(st[r], st[r+4]);
            // c=6: reg b1 -> flip reg b0
            #pragma unroll
            for (int r = 0; r < 32; r++) if ((r & 2) && !(r & 1)) SWAPF(st[r], st[r+1]);
            // fused lane perm: c=0 then c=1
            #pragma unroll
            for (int r = 0; r < 32; r++) st[r] = __shfl_sync(FULLMASK, st[r], psrc);
            // c=3: reg b4 -> flip reg b3
            #pragma unroll
            for (int r = 0; r < 32; r++) if ((r & 16) && !(r & 8)) SWAPF(st[r], st[r+8]);
            // c=5: reg b2 -> flip reg b1
            #pragma unroll
            for (int r = 0; r < 32; r++) if ((r & 4) && !(r & 2)) SWAPF(st[r], st[r+2]);

            // RY lane qubits q0..q2 (masks 4,2,1)
            #pragma unroll
            for (int q = 0; q < 3; q++) {
                const int bm = 4 >> q;
                float2 cs = sh_wcs[w][lyr][q];
                float sgn = (lane & bm) ? cs.y : -cs.y;
                #pragma unroll
                for (int r = 0; r < 32; r++) {
                    float o = __shfl_xor_sync(FULLMASK, st[r], bm);
                    st[r] = fmaf(sgn, o, cs.x * st[r]);
                }
            }
            // RY reg qubits q3..q7
            #pragma unroll
            for (int q = 3; q < 8; q++) {
                const int s = 1 << (7 - q);
                float2 cs = sh_wcs[w][lyr][q];
                #pragma unroll
                for (int r = 0; r < 32; r++) if (!(r & s)) {
                    float a0 = st[r], a1 = st[r+s];
                    st[r] = cs.x*a0 - cs.y*a1; st[r+s] = cs.y*a0 + cs.x*a1;
                }
            }
        }

        // measurement
        {
            float p[32];
            #pragma unroll
            for (int r = 0; r < 32; r++) p[r] = st[r]*st[r];
            float s16[16], s8[8], s4[4], s2[2];
            float z7=0, z6=0, z5=0, z4=0;
            #pragma unroll
            for (int k = 0; k < 16; k++) { s16[k] = p[2*k]+p[2*k+1]; z7 += p[2*k]-p[2*k+1]; }
            #pragma unroll
            for (int k = 0; k < 8;  k++) { s8[k] = s16[2*k]+s16[2*k+1]; z6 += s16[2*k]-s16[2*k+1]; }
            #pragma unroll
            for (int k = 0; k < 4;  k++) { s4[k] = s8[2*k]+s8[2*k+1]; z5 += s8[2*k]-s8[2*k+1]; }
            #pragma unroll
            for (int k = 0; k < 2;  k++) { s2[k] = s4[2*k]+s4[2*k+1]; z4 += s4[2*k]-s4[2*k+1]; }
            float z3 = s2[0]-s2[1], Tt = s2[0]+s2[1];
            float o, z0v, z1v, z2v;
            o = __shfl_xor_sync(FULLMASK, Tt, 1);
            z2v = (lane & 1) ? (o - Tt) : (Tt - o); Tt += o;
            z3 += __shfl_xor_sync(FULLMASK, z3, 1);
            z4 += __shfl_xor_sync(FULLMASK, z4, 1);
            z5 += __shfl_xor_sync(FULLMASK, z5, 1);
            z6 += __shfl_xor_sync(FULLMASK, z6, 1);
            z7 += __shfl_xor_sync(FULLMASK, z7, 1);
            o = __shfl_xor_sync(FULLMASK, Tt, 2);
            z1v = (lane & 2) ? (o - Tt) : (Tt - o); Tt += o;
            z2v += __shfl_xor_sync(FULLMASK, z2v, 2);
            z3 += __shfl_xor_sync(FULLMASK, z3, 2);
            z4 += __shfl_xor_sync(FULLMASK, z4, 2);
            z5 += __shfl_xor_sync(FULLMASK, z5, 2);
            z6 += __shfl_xor_sync(FULLMASK, z6, 2);
            z7 += __shfl_xor_sync(FULLMASK, z7, 2);
            o = __shfl_xor_sync(FULLMASK, Tt, 4);
            z0v = (lane & 4) ? (o - Tt) : (Tt - o);
            z1v += __shfl_xor_sync(FULLMASK, z1v, 4);
            z2v += __shfl_xor_sync(FULLMASK, z2v, 4);
            z3 += __shfl_xor_sync(FULLMASK, z3, 4);
            z4 += __shfl_xor_sync(FULLMASK, z4, 4);
            z5 += __shfl_xor_sync(FULLMASK, z5, 4);
            z6 += __shfl_xor_sync(FULLMASK, z6, 4);
            z7 += __shfl_xor_sync(FULLMASK, z7, 4);
            if (l == 0) {
                sh_z[j][w][0] = make_float4(z0v, z1v, z2v, z3);
                sh_z[j][w][1] = make_float4(z4, z5, z6, z7);
            }
        }
        __syncthreads();

        // Phase D
        #pragma unroll
        for (int e = 0; e < 4; e++) {
            float pre[4] = {bi, bf, bg, bo};
            #pragma unroll
            for (int g = 0; g < 4; g++) {
                float4 z0 = sh_z[e][g][0], z1 = sh_z[e][g][1];
                const float* pw = &pwr[g*8];
                pre[g] += z0.x*pw[0] + z0.y*pw[1] + z0.z*pw[2] + z0.w*pw[3]
                        + z1.x*pw[4] + z1.y*pw[5] + z1.z*pw[6] + z1.w*pw[7];
            }
            float i_t = 1.f/(1.f+expf(-pre[0]));
            float f_t = 1.f/(1.f+expf(-pre[1]));
            float g_t = tanhf(pre[2]);
            float o_t = 1.f/(1.f+expf(-pre[3]));
            c_e[e] = f_t*c_e[e] + i_t*g_t;
            h_e[e] = o_t*tanhf(c_e[e]);
            float v = h_e[e] + emb_e[e];
            float r0 = warp_sum(v), r1 = warp_sum(v*v), r2 = warp_sum(v*gw);
            if (lane == 0) sh_redB[w][e] = make_float4(r0, r1, r2, 0.f);
        }
        __syncthreads();
        if (tid < 4) {
            float Sv=0, Sq=0, Sg=0;
            #pragma unroll
            for (int ww = 0; ww < 4; ww++) {
                float4 r = sh_redB[ww][tid];
                Sv += r.x; Sq += r.y; Sg += r.z;
            }
            float m2 = Sv * (1.f/128.f);
            float inv2 = rsqrtf(Sq * (1.f/128.f) - m2*m2 + EPS_);
            out[(size_t)(b0 + tid) * T_ + t] = inv2 * (Sg - m2 * S1) + C0;
        }
    }
}

extern "C" void kernel_launch(void* const* d_in, const int* in_sizes, int n_in,
                              void* d_out, int out_size) {
    const float* p[26];
    for (int i = 0; i < 26; i++) p[i] = (const float*)d_in[i];
    emb_kernel<<<1024, 128>>>(p[0], p[1], p[2], p[3], p[4], p[5]);
    pj_kernel<<<1024, 128>>>(p[6]);
    qlstm_kernel<<<256, 128>>>(
        p[6], p[7], p[8], p[9], p[10], p[11], p[12], p[13],
        p[14], p[15], p[16], p[17], p[18], p[19], p[20], p[21],
        p[22], p[23], p[24], p[25], (float*)d_out);
}

// round 6
// speedup vs baseline: 1.2404x; 1.1451x over previous
#include <cuda_runtime.h>
#include <cuda_bf16.h>
#include <math.h>

#define FULLMASK 0xffffffffu
#define SWAPF(a,b) { float _t=(a); (a)=(b); (b)=_t; }

constexpr int T_ = 128;
constexpr int H_ = 128;
constexpr float EPS_ = 1e-5f;
constexpr float R2_ = 0.70710678118654752440f;

__device__ float g_emb[1024 * 128 * 128];   // LN(emb)+pe
__device__ float g_pj[1024 * 128 * 8];      // emb-half of proj dot

__device__ __forceinline__ float warp_sum(float v) {
    v += __shfl_xor_sync(FULLMASK, v, 16);
    v += __shfl_xor_sync(FULLMASK, v, 8);
    v += __shfl_xor_sync(FULLMASK, v, 4);
    v += __shfl_xor_sync(FULLMASK, v, 2);
    v += __shfl_xor_sync(FULLMASK, v, 1);
    return v;
}
__device__ __forceinline__ float sigf(float x)  { return 1.f / (1.f + __expf(-x)); }
__device__ __forceinline__ float tanhff(float x){ return 1.f - 2.f / (1.f + __expf(2.f * x)); }

// ---------------- kernel 1: embeddings ----------------
__global__ __launch_bounds__(128)
void emb_kernel(const float* __restrict__ x, const float* __restrict__ pe,
                const float* __restrict__ emb_w, const float* __restrict__ emb_b,
                const float* __restrict__ emb_g, const float* __restrict__ emb_bt)
{
    const int e = blockIdx.x, tid = threadIdx.x, w = tid >> 5, lane = tid & 31;
    __shared__ __align__(16) float sx[T_ * 8];
    const float4* xg = (const float4*)(x + (size_t)e * T_ * 8);
    ((float4*)sx)[tid] = xg[tid];
    ((float4*)sx)[tid + 128] = xg[tid + 128];

    float ew[4][8], gb[4], bt[4], bb[4];
    #pragma unroll
    for (int m = 0; m < 4; m++) {
        int h = lane + 32 * m;
        #pragma unroll
        for (int k = 0; k < 8; k++) ew[m][k] = emb_w[h * 8 + k];
        gb[m] = emb_g[h]; bt[m] = emb_bt[h]; bb[m] = emb_b[h];
    }
    __syncthreads();
    for (int it = 0; it < 32; it++) {
        int t = it * 4 + w;
        const float* xr = sx + t * 8;
        float e4[4];
        #pragma unroll
        for (int m = 0; m < 4; m++) {
            float s = bb[m];
            #pragma unroll
            for (int k = 0; k < 8; k++) s += xr[k] * ew[m][k];
            e4[m] = s;
        }
        float s = (e4[0]+e4[1])+(e4[2]+e4[3]);
        float q = (e4[0]*e4[0]+e4[1]*e4[1])+(e4[2]*e4[2]+e4[3]*e4[3]);
        s = warp_sum(s); q = warp_sum(q);
        float m_ = s * (1.f/128.f);
        float inv = rsqrtf(q * (1.f/128.f) - m_*m_ + EPS_);
        #pragma unroll
        for (int m = 0; m < 4; m++) {
            int h = lane + 32 * m;
            g_emb[(size_t)e*T_*H_ + t*H_ + h] = (e4[m]-m_)*inv*gb[m] + bt[m] + __ldg(pe + t*H_ + h);
        }
    }
}

// ---------------- kernel 2: emb-half of proj dot ----------------
__global__ __launch_bounds__(128)
void pj_kernel(const float* __restrict__ ip_w)
{
    const int e = blockIdx.x, tid = threadIdx.x, w = tid >> 5, lane = tid & 31;
    __shared__ float2 sw[4][128];
    for (int i = tid; i < 512; i += 128) {
        int wp = i >> 7, k = i & 127;
        sw[wp][k] = make_float2(ip_w[2*wp*256 + k], ip_w[(2*wp+1)*256 + k]);
    }
    __syncthreads();
    const float* eb = g_emb + (size_t)e * T_ * H_;
    for (int t = 0; t < T_; t++) {
        const float* er = eb + t * H_;
        float d0 = 0.f, d1 = 0.f;
        #pragma unroll
        for (int i = 0; i < 4; i++) {
            int k = lane + 32 * i;
            float v = er[k]; float2 p = sw[w][k];
            d0 += v * p.x; d1 += v * p.y;
        }
        d0 = warp_sum(d0); d1 = warp_sum(d1);
        if (lane == 0) ((float2*)(g_pj + ((size_t)e*T_ + t)*8))[w] = make_float2(d0, d1);
    }
}

// ---------------- kernel 3: recurrence. P=16, 2 elems/CTA, warp=gate ----------------
__global__ __launch_bounds__(128, 4)
void qlstm_kernel(
    const float* __restrict__ ip_w,  const float* __restrict__ ip_b,
    const float* __restrict__ in_g,  const float* __restrict__ in_b,
    const float* __restrict__ wq_i,  const float* __restrict__ wq_f,
    const float* __restrict__ wq_g,  const float* __restrict__ wq_o,
    const float* __restrict__ pi_w,  const float* __restrict__ pi_b,
    const float* __restrict__ pf_w,  const float* __restrict__ pf_b,
    const float* __restrict__ pg_w,  const float* __restrict__ pg_b,
    const float* __restrict__ po_w,  const float* __restrict__ po_b,
    const float* __restrict__ on_g,  const float* __restrict__ on_b,
    const float* __restrict__ out_w, const float* __restrict__ out_b,
    float* __restrict__ out)
{
    const int b0 = blockIdx.x * 2;
    const int tid = threadIdx.x, w = tid >> 5, lane = tid & 31;
    const int ll = lane & 15, g2 = lane >> 4;   // group = elem for VQC
    const int h = tid;

    __shared__ __align__(16) float  sh_hs[2][132];
    __shared__ __align__(16) float2 sh_wcs[4][4][8];
    __shared__ __align__(16) float2 sh_incs[2][8];
    __shared__ __align__(16) float2 sh_pj[2][4];    // [elem][warp-pair] -> outputs 0..7
    __shared__ __align__(16) float4 sh_z[2][4][2];  // [elem][gate]
    __shared__ __align__(16) float4 sh_redB[4][2];  // [warp][elem]
    __shared__ float sh_sc[2], sh_ing8[8], sh_inb8[8];

    // ---- staging ----
    {
        const float* wq[4] = {wq_i, wq_f, wq_g, wq_o};
        int g = tid >> 5, rem = tid & 31, lyr = rem >> 3, q = rem & 7;
        float a = 0.5f * wq[g][lyr * 8 + q];
        sh_wcs[g][lyr][q] = make_float2(cosf(a), sinf(a));
    }
    if (tid < 8) { sh_ing8[tid] = in_g[tid]; sh_inb8[tid] = in_b[tid]; }

    // Phase-B weights (h-half of ip_w rows 2w, 2w+1) in registers
    float wb0[4], wb1[4];
    #pragma unroll
    for (int i = 0; i < 4; i++) {
        wb0[i] = ip_w[(2*w)   * 256 + 128 + lane + 32*i];
        wb1[i] = ip_w[(2*w+1) * 256 + 128 + lane + 32*i];
    }
    // Phase-D gate weights for this thread's h
    float pwr[32];
    {
        const float* pw[4] = {pi_w, pf_w, pg_w, po_w};
        #pragma unroll
        for (int g = 0; g < 4; g++)
            #pragma unroll
            for (int q = 0; q < 8; q++) pwr[g*8+q] = pw[g][h*8+q];
    }
    const float gw = on_g[h]*out_w[h], bwv = on_b[h]*out_w[h];
    const float bi = pi_b[h], bf = pf_b[h], bg = pg_b[h], bo = po_b[h];
    const float ipb0 = ip_b[2*w], ipb1 = ip_b[2*w+1];

    {
        float s1 = warp_sum(gw), s2 = warp_sum(bwv);
        if (lane == 0) sh_redB[w][0] = make_float4(s1, s2, 0.f, 0.f);
    }
    __syncthreads();
    if (tid == 0) {
        float S = 0.f, C = 0.f;
        #pragma unroll
        for (int i = 0; i < 4; i++) { S += sh_redB[i][0].x; C += sh_redB[i][0].y; }
        sh_sc[0] = S; sh_sc[1] = C + out_b[0];
    }
    __syncthreads();
    const float S1 = sh_sc[0], C0 = sh_sc[1];

    // fused lane perm (c0: l2^=l3, c2: l0^=l1, then c1: l1^=l2'):
    // inverse: s3=l3, s2=l2^l3, s1=l1^l2, s0=l0^l1^l2
    const int psrc = (((ll ^ (ll >> 1) ^ ((ll >> 2) & 1)) & 15)) | (lane & 16);
    const bool c3p = (lane & 1);   // c=3: q3 (lane b0) controls reg-bit3 flip

    float h_c[2] = {0.f, 0.f}, c_c[2] = {0.f, 0.f};
    const size_t estr = (size_t)T_ * H_;
    const float* embbase = g_emb + (size_t)b0 * estr;

    for (int t = 0; t < T_; t++) {
        float emb_e[2];
        #pragma unroll
        for (int e = 0; e < 2; e++) {
            sh_hs[e][h] = h_c[e];
            emb_e[e] = __ldg(embbase + e * estr + t * H_ + h);
        }
        __syncthreads();

        // ---- Phase B: h-half dots for outputs 2w, 2w+1, both elems ----
        {
            float d00 = 0.f, d01 = 0.f, d10 = 0.f, d11 = 0.f;
            #pragma unroll
            for (int i = 0; i < 4; i++) {
                int k = lane + 32 * i;
                float c0v = sh_hs[0][k], c1v = sh_hs[1][k];
                d00 += c0v * wb0[i]; d01 += c0v * wb1[i];
                d10 += c1v * wb0[i]; d11 += c1v * wb1[i];
            }
            d00 = warp_sum(d00); d01 = warp_sum(d01);
            d10 = warp_sum(d10); d11 = warp_sum(d11);
            if (lane == 0) {
                float2 gp0 = __ldg((const float2*)(g_pj + ((size_t)(b0  )*T_ + t)*8) + w);
                float2 gp1 = __ldg((const float2*)(g_pj + ((size_t)(b0+1)*T_ + t)*8) + w);
                sh_pj[0][w] = make_float2(d00 + gp0.x + ipb0, d01 + gp0.y + ipb1);
                sh_pj[1][w] = make_float2(d10 + gp1.x + ipb0, d11 + gp1.y + ipb1);
            }
        }
        __syncthreads();

        // ---- mini-LN(8) + input angles (warp 0; lanes 0..15 active pattern) ----
        if (w == 0) {
            int e = (lane >> 3) & 1, q = lane & 7;
            float pv = tanhff(((const float*)&sh_pj[e][0])[q]);
            float sm = pv, sq = pv*pv;
            sm += __shfl_xor_sync(FULLMASK, sm, 1); sq += __shfl_xor_sync(FULLMASK, sq, 1);
            sm += __shfl_xor_sync(FULLMASK, sm, 2); sq += __shfl_xor_sync(FULLMASK, sq, 2);
            sm += __shfl_xor_sync(FULLMASK, sm, 4); sq += __shfl_xor_sync(FULLMASK, sq, 4);
            float mm = sm * 0.125f;
            float iv = rsqrtf(sq * 0.125f - mm*mm + EPS_);
            float a = 0.5f * ((pv - mm) * iv * sh_ing8[q] + sh_inb8[q]);
            if (lane < 16) {
                float ss, cc; __sincosf(a, &ss, &cc);
                sh_incs[e][q] = make_float2(cc, ss);
            }
        }
        __syncthreads();

        // ---- Phase C: VQC. lane bits(3..0)=qubits(0..3); reg bits(3..0)=qubits(4..7) ----
        float st[16];
        {
            float F0[8], F1[8];
            #pragma unroll
            for (int q = 0; q < 8; q++) {
                float2 cs = sh_incs[g2][q];
                F0[q] = R2_ * (cs.x - cs.y); F1[q] = R2_ * (cs.x + cs.y);
            }
            st[0] = ((ll&8)?F1[0]:F0[0]) * ((ll&4)?F1[1]:F0[1])
                  * ((ll&2)?F1[2]:F0[2]) * ((ll&1)?F1[3]:F0[3]);
            #pragma unroll
            for (int q = 4; q < 8; q++) {
                int s = 1 << (7 - q);
                #pragma unroll
                for (int r = 0; r < 16; r += 2*s) {
                    float v = st[r];
                    st[r] = v * F0[q]; st[r+s] = v * F1[q];
                }
            }
        }

        #pragma unroll
        for (int lyr = 0; lyr < 4; lyr++) {
            // c=4: reg b3 -> flip reg b2
            #pragma unroll
            for (int r = 8; r < 12; r++) SWAPF(st[r], st[r+4]);
            // c=6: reg b1 -> flip reg b0
            #pragma unroll
            for (int r = 2; r < 16; r += 4) SWAPF(st[r], st[r+1]);
            // fused lane perm: c0, c2, c1
            #pragma unroll
            for (int r = 0; r < 16; r++) st[r] = __shfl_sync(FULLMASK, st[r], psrc);
            // c=5: reg b2 -> flip reg b1
            #pragma unroll
            for (int r = 4; r < 16; r += 8) { SWAPF(st[r], st[r+2]); SWAPF(st[r+1], st[r+3]); }
            // c=3: lane b0 -> flip reg b3 (predicated)
            #pragma unroll
            for (int r = 0; r < 8; r++) {
                float a = st[r], b2 = st[r+8];
                st[r] = c3p ? b2 : a; st[r+8] = c3p ? a : b2;
            }

            // RY lane qubits q0..q3 (masks 8,4,2,1)
            #pragma unroll
            for (int q = 0; q < 4; q++) {
                const int bm = 8 >> q;
                float2 cs = sh_wcs[w][lyr][q];
                float sgn = (lane & bm) ? cs.y : -cs.y;
                #pragma unroll
                for (int r = 0; r < 16; r++) {
                    float o = __shfl_xor_sync(FULLMASK, st[r], bm);
                    st[r] = fmaf(sgn, o, cs.x * st[r]);
                }
            }
            // RY reg qubits q4..q7 (strides 8,4,2,1)
            #pragma unroll
            for (int q = 4; q < 8; q++) {
                const int s = 1 << (7 - q);
                float2 cs = sh_wcs[w][lyr][q];
                #pragma unroll
                for (int r = 0; r < 16; r++) if (!(r & s)) {
                    float a0 = st[r], a1 = st[r+s];
                    st[r] = cs.x*a0 - cs.y*a1; st[r+s] = cs.y*a0 + cs.x*a1;
                }
            }
        }

        // ---- measurement ----
        {
            float p[16];
            #pragma unroll
            for (int r = 0; r < 16; r++) p[r] = st[r]*st[r];
            float s8[8], s4[4], s2[2];
            float z7=0, z6=0, z5=0;
            #pragma unroll
            for (int k = 0; k < 8; k++) { s8[k] = p[2*k]+p[2*k+1]; z7 += p[2*k]-p[2*k+1]; }
            #pragma unroll
            for (int k = 0; k < 4; k++) { s4[k] = s8[2*k]+s8[2*k+1]; z6 += s8[2*k]-s8[2*k+1]; }
            #pragma unroll
            for (int k = 0; k < 2; k++) { s2[k] = s4[2*k]+s4[2*k+1]; z5 += s4[2*k]-s4[2*k+1]; }
            float z4 = s2[0]-s2[1], Tt = s2[0]+s2[1];
            float o, z0v, z1v, z2v, z3v;

            o = __shfl_xor_sync(FULLMASK, Tt, 1);
            z3v = (lane & 1) ? (o - Tt) : (Tt - o); Tt += o;
            z4 += __shfl_xor_sync(FULLMASK, z4, 1);
            z5 += __shfl_xor_sync(FULLMASK, z5, 1);
            z6 += __shfl_xor_sync(FULLMASK, z6, 1);
            z7 += __shfl_xor_sync(FULLMASK, z7, 1);

            o = __shfl_xor_sync(FULLMASK, Tt, 2);
            z2v = (lane & 2) ? (o - Tt) : (Tt - o); Tt += o;
            z3v += __shfl_xor_sync(FULLMASK, z3v, 2);
            z4 += __shfl_xor_sync(FULLMASK, z4, 2);
            z5 += __shfl_xor_sync(FULLMASK, z5, 2);
            z6 += __shfl_xor_sync(FULLMASK, z6, 2);
            z7 += __shfl_xor_sync(FULLMASK, z7, 2);

            o = __shfl_xor_sync(FULLMASK, Tt, 4);
            z1v = (lane & 4) ? (o - Tt) : (Tt - o); Tt += o;
            z2v += __shfl_xor_sync(FULLMASK, z2v, 4);
            z3v += __shfl_xor_sync(FULLMASK, z3v, 4);
            z4 += __shfl_xor_sync(FULLMASK, z4, 4);
            z5 += __shfl_xor_sync(FULLMASK, z5, 4);
            z6 += __shfl_xor_sync(FULLMASK, z6, 4);
            z7 += __shfl_xor_sync(FULLMASK, z7, 4);

            o = __shfl_xor_sync(FULLMASK, Tt, 8);
            z0v = (lane & 8) ? (o - Tt) : (Tt - o);
            z1v += __shfl_xor_sync(FULLMASK, z1v, 8);
            z2v += __shfl_xor_sync(FULLMASK, z2v, 8);
            z3v += __shfl_xor_sync(FULLMASK, z3v, 8);
            z4 += __shfl_xor_sync(FULLMASK, z4, 8);
            z5 += __shfl_xor_sync(FULLMASK, z5, 8);
            z6 += __shfl_xor_sync(FULLMASK, z6, 8);
            z7 += __shfl_xor_sync(FULLMASK, z7, 8);

            if (ll == 0) {
                sh_z[g2][w][0] = make_float4(z0v, z1v, z2v, z3v);
                sh_z[g2][w][1] = make_float4(z4, z5, z6, z7);
            }
        }
        __syncthreads();

        // ---- Phase D: gates, LSTM update, output LN ----
        #pragma unroll
        for (int e = 0; e < 2; e++) {
            float pre[4] = {bi, bf, bg, bo};
            #pragma unroll
            for (int g = 0; g < 4; g++) {
                float4 z0 = sh_z[e][g][0], z1 = sh_z[e][g][1];
                const float* pw = &pwr[g*8];
                pre[g] += z0.x*pw[0] + z0.y*pw[1] + z0.z*pw[2] + z0.w*pw[3]
                        + z1.x*pw[4] + z1.y*pw[5] + z1.z*pw[6] + z1.w*pw[7];
            }
            float i_t = sigf(pre[0]);
            float f_t = sigf(pre[1]);
            float g_t = tanhff(pre[2]);
            float o_t = sigf(pre[3]);
            c_c[e] = f_t*c_c[e] + i_t*g_t;
            h_c[e] = o_t*tanhff(c_c[e]);
            float v = h_c[e] + emb_e[e];
            float r0 = warp_sum(v), r1 = warp_sum(v*v), r2 = warp_sum(v*gw);
            if (lane == 0) sh_redB[w][e] = make_float4(r0, r1, r2, 0.f);
        }
        __syncthreads();
        if (tid < 2) {
            float Sv=0, Sq=0, Sg=0;
            #pragma unroll
            for (int ww = 0; ww < 4; ww++) {
                float4 r = sh_redB[ww][tid];
                Sv += r.x; Sq += r.y; Sg += r.z;
            }
            float m2 = Sv * (1.f/128.f);
            float inv2 = rsqrtf(Sq * (1.f/128.f) - m2*m2 + EPS_);
            out[(size_t)(b0 + tid) * T_ + t] = inv2 * (Sg - m2 * S1) + C0;
        }
    }
}

extern "C" void kernel_launch(void* const* d_in, const int* in_sizes, int n_in,
                              void* d_out, int out_size) {
    const float* p[26];
    for (int i = 0; i < 26; i++) p[i] = (const float*)d_in[i];
    emb_kernel<<<1024, 128>>>(p[0], p[1], p[2], p[3], p[4], p[5]);
    pj_kernel<<<1024, 128>>>(p[6]);
    qlstm_kernel<<<512, 128>>>(
        p[6], p[7], p[8], p[9], p[10], p[11], p[12], p[13],
        p[14], p[15], p[16], p[17], p[18], p[19], p[20], p[21],
        p[22], p[23], p[24], p[25], (float*)d_out);
}